// round 14
// baseline (speedup 1.0000x reference)
#include <cuda_runtime.h>
#include <math.h>

#define BB 8
#define LL 48000
#define VV 28
#define QQ 256
#define CC 256
#define TT 960          // L / 50
#define NGD 29          // V + 1

#define ENC_BLOCKS 120          // 8 b * 15 chunks of 64 t
#define TBL_BLOCKS 28           // i blocks; block 27 also does i=28
#define LOSS_BLOCKS 375         // 384000 / (256*4)

// ---------------- scratch ----------------
__device__ int    g_preds[BB * TT];
__device__ float  g_M[NGD * 5 * 10 * 256];    // logprob table: acc + bd2 - LSE
__device__ double g_prec[LOSS_BLOCKS];
__device__ double g_pkl[LOSS_BLOCKS];
__device__ int    g_ticket;                   // zero-init; self-resets each pass

// ---------------- f32x2 helpers ----------------
__device__ __forceinline__ void fma2(unsigned long long& d, unsigned long long a,
                                     unsigned long long b, unsigned long long c) {
    asm("fma.rn.f32x2 %0, %1, %2, %3;" : "=l"(d) : "l"(a), "l"(b), "l"(c));
}
__device__ __forceinline__ void add2(unsigned long long& d, unsigned long long a,
                                     unsigned long long b) {
    asm("add.rn.f32x2 %0, %1, %2;" : "=l"(d) : "l"(a), "l"(b));
}
__device__ __forceinline__ unsigned long long bcast2(float v) {
    unsigned long long r;
    asm("mov.b64 %0, {%1, %1};" : "=l"(r) : "f"(v));
    return r;
}
__device__ __forceinline__ void unpack2(unsigned long long v, float& lo, float& hi) {
    asm("mov.b64 {%0, %1}, %2;" : "=f"(lo), "=f"(hi) : "l"(v));
}

// ---------------- encoder smem layout (unchanged quarter-split) ----------------
#define W2STRIDE 164
#define W1STRIDE 14
#define ENC_T    64
#define LSTRIDE  33
#define W2S_OFF 0
#define W1S_OFF (256 * W2STRIDE)
#define XS_OFF  (W1S_OFF + 256 * W1STRIDE)
#define B1S_OFF (XS_OFF + ENC_T * 50)
#define B2S_OFF (B1S_OFF + 256)
#define LS_OFF  (B2S_OFF + 32)
#define ENC_SMEM_FLOATS (LS_OFF + ENC_T * LSTRIDE)
#define ENC_SMEM_BYTES  (ENC_SMEM_FLOATS * 4)       // ~204.7 KB

// ---------------- table smem layout (within same dynamic smem) ----------------
#define TILE_C   8                                   // c rows per chunk
#define TILE_FLOATS (TILE_C * 2560)                  // 20480
#define RV_OFF   TILE_FLOATS
#define RED_OFF  (RV_OFF + 1280)                     // red2[50][8]
#define MALL_OFF (RED_OFF + 400)
#define LSE_OFF  (MALL_OFF + 50)

// table routine: one i, 512 threads (256 compute, all stage/sync)
__device__ void table_block(float* sm, int i, int i28,
                            const float* __restrict__ Wd1,
                            const float* __restrict__ bd1,
                            const float* __restrict__ Wd2,
                            const float* __restrict__ bd2)
{
    float* tile = sm;
    float* rv   = sm + RV_OFF;
    float* red2 = sm + RED_OFF;
    float* mall = sm + MALL_OFF;
    float* lses = sm + LSE_OFF;
    const int tid = threadIdx.x;

    // rv[j2*256+c] = clip(Wd1[i,c,j2] + bd1[c]); i28: only row 0 (= clip(bd1))
    for (int lin = tid; lin < 1280; lin += 512) {
        int c = lin / 5, j2 = lin % 5;
        float w = i28 ? 0.f : Wd1[i * 1280 + lin];
        rv[j2 * 256 + c] = fminf(fmaxf(w + bd1[c], 0.f), 6.f);
    }
    __syncthreads();

    const int q = tid;              // compute threads: tid < 256
    unsigned long long acc2[25];
#pragma unroll
    for (int a = 0; a < 25; a++) acc2[a] = 0ULL;

    for (int chunk = 0; chunk < 32; chunk++) {
        __syncthreads();            // protect tile from previous compute
        const float4* src = (const float4*)(Wd2 + chunk * TILE_FLOATS);
        float4* t4 = (float4*)tile;
#pragma unroll
        for (int k = 0; k < 10; k++)
            t4[tid + 512 * k] = src[tid + 512 * k];   // coalesced
        __syncthreads();
        if (tid < 256) {
#pragma unroll
            for (int cc = 0; cc < TILE_C; cc++) {
                const int c = chunk * TILE_C + cc;
                const unsigned long long* wrow =
                    (const unsigned long long*)(tile + cc * 2560 + q * 10);
                const unsigned long long w0 = wrow[0], w1 = wrow[1],
                                         w2 = wrow[2], w3 = wrow[3], w4 = wrow[4];
                if (!i28) {
#pragma unroll
                    for (int j2 = 0; j2 < 5; j2++) {
                        const unsigned long long hp = bcast2(rv[j2 * 256 + c]);
                        fma2(acc2[j2 * 5 + 0], hp, w0, acc2[j2 * 5 + 0]);
                        fma2(acc2[j2 * 5 + 1], hp, w1, acc2[j2 * 5 + 1]);
                        fma2(acc2[j2 * 5 + 2], hp, w2, acc2[j2 * 5 + 2]);
                        fma2(acc2[j2 * 5 + 3], hp, w3, acc2[j2 * 5 + 3]);
                        fma2(acc2[j2 * 5 + 4], hp, w4, acc2[j2 * 5 + 4]);
                    }
                } else {
                    const unsigned long long hp = bcast2(rv[c]);
                    fma2(acc2[0], hp, w0, acc2[0]);
                    fma2(acc2[1], hp, w1, acc2[1]);
                    fma2(acc2[2], hp, w2, acc2[2]);
                    fma2(acc2[3], hp, w3, acc2[3]);
                    fma2(acc2[4], hp, w4, acc2[4]);
                }
            }
        }
    }
    __syncthreads();

    // v[p] = acc(j2=p/10, j=p%10) + bd2[q];  npairs = 50 (or 10 for i28, j2=0)
    const int npairs = i28 ? 10 : 50;
    float accf[50];
    float bdq = 0.f;
    if (tid < 256) {
        bdq = bd2[tid];
#pragma unroll
        for (int a = 0; a < 25; a++) unpack2(acc2[a], accf[2 * a], accf[2 * a + 1]);
    }
    const int lane = tid & 31, wid = tid >> 5;

    // phase A: per-warp max
    if (tid < 256) {
        for (int p = 0; p < npairs; p++) {
            const int j2 = p / 10, j = p % 10;
            float v = accf[(j2 * 5 + (j >> 1)) * 2 + (j & 1)] + bdq;
            float m = v;
            for (int s = 16; s > 0; s >>= 1)
                m = fmaxf(m, __shfl_xor_sync(0xffffffffu, m, s));
            if (lane == 0) red2[p * 8 + wid] = m;
        }
    }
    __syncthreads();
    // phase B: cross-warp max (sequential, matches old order red[0], fmax 1..7)
    if (tid < npairs) {
        float mAll = red2[tid * 8];
#pragma unroll
        for (int w2 = 1; w2 < 8; w2++) mAll = fmaxf(mAll, red2[tid * 8 + w2]);
        mall[tid] = mAll;
    }
    __syncthreads();
    // phase C: per-warp exp-sum
    if (tid < 256) {
        for (int p = 0; p < npairs; p++) {
            const int j2 = p / 10, j = p % 10;
            float v = accf[(j2 * 5 + (j >> 1)) * 2 + (j & 1)] + bdq;
            float e = expf(v - mall[p]);
            for (int s = 16; s > 0; s >>= 1)
                e += __shfl_xor_sync(0xffffffffu, e, s);
            if (lane == 0) red2[p * 8 + wid] = e;
        }
    }
    __syncthreads();
    // phase D: cross-warp sum (ascending, matches old)
    if (tid < npairs) {
        float ssum = 0.f;
#pragma unroll
        for (int w2 = 0; w2 < 8; w2++) ssum += red2[tid * 8 + w2];
        lses[tid] = mall[tid] + logf(ssum);
    }
    __syncthreads();
    // phase E: store logprob
    if (tid < 256) {
        if (!i28) {
            for (int p = 0; p < 50; p++) {
                const int j2 = p / 10, j = p % 10;
                float v = accf[(j2 * 5 + (j >> 1)) * 2 + (j & 1)] + bdq;
                g_M[((i * 5 + j2) * 10 + j) * 256 + tid] = v - lses[p];
            }
        } else {
            for (int j = 0; j < 10; j++) {
                float v = accf[(j >> 1) * 2 + (j & 1)] + bdq;
                float val = v - lses[j];
#pragma unroll
                for (int j2 = 0; j2 < 5; j2++)
                    g_M[((28 * 5 + j2) * 10 + j) * 256 + tid] = val;
            }
        }
    }
    __syncthreads();
}

// ---------------- fused encoder + decoder table (148 blocks = 1 wave) ----------------
__global__ __launch_bounds__(512, 1)
void k_enc_table(const float* __restrict__ x, const float* __restrict__ gumbel,
                 const float* __restrict__ W1, const float* __restrict__ b1,
                 const float* __restrict__ W2, const float* __restrict__ b2,
                 const float* __restrict__ Wd1, const float* __restrict__ bd1,
                 const float* __restrict__ Wd2, const float* __restrict__ bd2)
{
    extern __shared__ float sm[];
    const int tid = threadIdx.x;

    if (blockIdx.x >= ENC_BLOCKS) {
        const int i = blockIdx.x - ENC_BLOCKS;          // 0..27
        table_block(sm, i, 0, Wd1, bd1, Wd2, bd2);
        if (i == 27)                                     // block 27 also does i=28
            table_block(sm, 28, 1, Wd1, bd1, Wd2, bd2);
        return;
    }

    // ----- encoder branch (unchanged quarter-split) -----
    float* W2s = sm + W2S_OFF;
    float* W1s = sm + W1S_OFF;
    float* xs  = sm + XS_OFF;
    float* b1s = sm + B1S_OFF;
    float* b2s = sm + B2S_OFF;
    float* ls  = sm + LS_OFF;

    const int b   = blockIdx.x / 15;
    const int t0  = (blockIdx.x % 15) * ENC_T;

    for (int lin = tid; lin < 28 * 256 * 5; lin += 512) {
        int o = lin / 1280, rem = lin % 1280;
        int c = rem / 5,    kk  = rem % 5;
        int qd = o >> 3, oo = o & 7;
        W2s[c * W2STRIDE + qd * 40 + kk * 8 + oo] = W2[lin];
    }
    for (int lin = tid; lin < 256 * 5 * 4; lin += 512) {
        int c = lin / 20, kk = (lin % 20) / 4, oo = (lin % 4) + 4;
        W2s[c * W2STRIDE + 120 + kk * 8 + oo] = 0.f;
    }
    for (int lin = tid; lin < 2560; lin += 512)
        W1s[(lin / 10) * W1STRIDE + (lin % 10)] = W1[lin];
    for (int lin = tid; lin < ENC_T * 50; lin += 512)
        xs[lin] = x[b * LL + t0 * 50 + lin];
    if (tid < 256) b1s[tid] = b1[tid];
    if (tid < 28)  b2s[tid] = b2[tid];
    __syncthreads();

    const int s   = tid >> 3;
    const int cg  = tid & 7;
    const int oq  = s & 3;

    const unsigned long long* xsp = (const unsigned long long*)(xs + 50 * s);
    unsigned long long xr2[25];
#pragma unroll
    for (int j = 0; j < 25; j++) xr2[j] = xsp[j];

    unsigned long long acc[4][4];
#pragma unroll
    for (int r = 0; r < 4; r++)
#pragma unroll
        for (int u = 0; u < 4; u++) acc[r][u] = 0ULL;

    for (int ci = 0; ci < 32; ci++) {
        const int c = cg + 8 * ci;
        const unsigned long long* w1p = (const unsigned long long*)(W1s + c * W1STRIDE);
        const float b1c = b1s[c];
        const float* wq = W2s + c * W2STRIDE + oq * 40;

#pragma unroll
        for (int kk = 0; kk < 5; kk++) {
            unsigned long long s2 = 0ULL;
#pragma unroll
            for (int k2 = 0; k2 < 5; k2++)
                fma2(s2, xr2[kk * 5 + k2], w1p[k2], s2);
            float lo, hi; unpack2(s2, lo, hi);
            const float h0 = fminf(fmaxf(lo + hi + b1c, 0.f), 6.f);
            const float h1 = __shfl_xor_sync(0xffffffffu, h0, 8);
            const float h2 = __shfl_xor_sync(0xffffffffu, h0, 16);
            const float h3 = __shfl_xor_sync(0xffffffffu, h1, 16);

            const ulonglong2* wp = (const ulonglong2*)(wq + kk * 8);
            const ulonglong2 w01 = wp[0];
            const ulonglong2 w23 = wp[1];

            const unsigned long long hp0 = bcast2(h0);
            const unsigned long long hp1 = bcast2(h1);
            const unsigned long long hp2 = bcast2(h2);
            const unsigned long long hp3 = bcast2(h3);

            fma2(acc[0][0], hp0, w01.x, acc[0][0]);
            fma2(acc[0][1], hp0, w01.y, acc[0][1]);
            fma2(acc[0][2], hp0, w23.x, acc[0][2]);
            fma2(acc[0][3], hp0, w23.y, acc[0][3]);
            fma2(acc[1][0], hp1, w01.x, acc[1][0]);
            fma2(acc[1][1], hp1, w01.y, acc[1][1]);
            fma2(acc[1][2], hp1, w23.x, acc[1][2]);
            fma2(acc[1][3], hp1, w23.y, acc[1][3]);
            fma2(acc[2][0], hp2, w01.x, acc[2][0]);
            fma2(acc[2][1], hp2, w01.y, acc[2][1]);
            fma2(acc[2][2], hp2, w23.x, acc[2][2]);
            fma2(acc[2][3], hp2, w23.y, acc[2][3]);
            fma2(acc[3][0], hp3, w01.x, acc[3][0]);
            fma2(acc[3][1], hp3, w01.y, acc[3][1]);
            fma2(acc[3][2], hp3, w23.x, acc[3][2]);
            fma2(acc[3][3], hp3, w23.y, acc[3][3]);
        }
    }

#pragma unroll
    for (int r = 0; r < 4; r++)
#pragma unroll
        for (int u = 0; u < 4; u++) {
            unsigned long long v = acc[r][u], o2;
            o2 = __shfl_xor_sync(0xffffffffu, v, 1); add2(v, v, o2);
            o2 = __shfl_xor_sync(0xffffffffu, v, 2); add2(v, v, o2);
            o2 = __shfl_xor_sync(0xffffffffu, v, 4); add2(v, v, o2);
            acc[r][u] = v;
        }

    if (cg == 0) {
        const int sbase = s & ~3;
#pragma unroll
        for (int r = 0; r < 4; r++) {
            const int tloc = sbase + ((s & 3) ^ r);
            float* lrow = ls + tloc * LSTRIDE + oq * 8;
#pragma unroll
            for (int u = 0; u < 4; u++) {
                float lo, hi; unpack2(acc[r][u], lo, hi);
                lrow[2 * u]     = lo;
                lrow[2 * u + 1] = hi;
            }
        }
    }
    __syncthreads();

    if (tid < ENC_T) {
        const int tg = t0 + tid;
        const float* g = gumbel + (b * TT + tg) * VV;
        const float* lrow = ls + tid * LSTRIDE;
        float best = -1e30f; int bi = 0;
#pragma unroll
        for (int o = 0; o < 28; o++) {
            float v = lrow[o] + b2s[o] + g[o];
            if (v > best) { best = v; bi = o; }
        }
        g_preds[b * TT + tg] = bi;
    }
}

// ---------------- loss (4 samples/thread) + fused final reduction ----------------
__global__ __launch_bounds__(256)
void k_loss(const float* __restrict__ x, const int* __restrict__ x_sl,
            const float* __restrict__ ngrams, float* __restrict__ out)
{
    __shared__ double sr[8], sk[8];
    __shared__ int    isLast;
    const int tid  = threadIdx.x;
    const int gid0 = (blockIdx.x * 256 + tid) * 4;      // < 384000
    const int b    = gid0 / LL;
    const int sl   = x_sl[b];
    const int zsl  = sl / 50;

    const float4 xv4 = *(const float4*)(x + gid0);
    const float xv[4] = {xv4.x, xv4.y, xv4.z, xv4.w};

    float rec = 0.f, kl = 0.f;
#pragma unroll
    for (int s = 0; s < 4; s++) {
        const int l = gid0 % LL + s;
        const int t = l / 50;
        if (l < sl) {
            float y = log1pf(255.f * fabsf(xv[s])) / 5.5451774444795625f;
            y = copysignf(y, xv[s]);
            int tq = (int)floorf((y + 1.0f) * 0.5f * 256.0f);
            tq = min(max(tq, 0), 255);
            const int j2 = (l / 10) % 5;
            const int j  = l % 10;
            const int i  = (t < zsl) ? g_preds[b * TT + t] : 28;
            rec -= g_M[(((i * 5 + j2) * 10 + j) * 256) + tq];
        }
        if ((l % 50) == 0 && t < zsl) {
            const int p  = g_preds[b * TT + t];
            const int a0 = (t >= 2) ? g_preds[b * TT + t - 2] : 28;
            const int a1 = (t >= 1) ? g_preds[b * TT + t - 1] : 28;
            const float pr = ngrams[(a0 * 29 + a1) * 28 + p];
            kl += logf(1.0f / (pr + 1e-10f) + 1e-10f);
        }
    }

    const int lane = tid & 31, wid = tid >> 5;
    for (int s = 16; s > 0; s >>= 1) {
        rec += __shfl_down_sync(0xffffffffu, rec, s);
        kl  += __shfl_down_sync(0xffffffffu, kl,  s);
    }
    if (lane == 0) { sr[wid] = (double)rec; sk[wid] = (double)kl; }
    __syncthreads();
    if (tid == 0) {
        double r = 0.0, k = 0.0;
#pragma unroll
        for (int w2 = 0; w2 < 8; w2++) { r += sr[w2]; k += sk[w2]; }
        g_prec[blockIdx.x] = r;
        g_pkl[blockIdx.x]  = k;
        __threadfence();
        int tck = atomicAdd(&g_ticket, 1);
        isLast = (tck == LOSS_BLOCKS - 1);
    }
    __syncthreads();

    if (isLast) {
        double r = 0.0, k = 0.0;
        for (int i = tid; i < LOSS_BLOCKS; i += 256) {
            r += __ldcg(&g_prec[i]);
            k += __ldcg(&g_pkl[i]);
        }
        for (int s = 16; s > 0; s >>= 1) {
            r += __shfl_down_sync(0xffffffffu, r, s);
            k += __shfl_down_sync(0xffffffffu, k, s);
        }
        __syncthreads();
        if (lane == 0) { sr[wid] = r; sk[wid] = k; }
        __syncthreads();
        if (tid == 0) {
            double R = 0.0, K = 0.0;
#pragma unroll
            for (int w2 = 0; w2 < 8; w2++) { R += sr[w2]; K += sk[w2]; }
            long long sx = 0, sz = 0;
#pragma unroll
            for (int bb = 0; bb < BB; bb++) { sx += x_sl[bb]; sz += x_sl[bb] / 50; }
            out[0] = (float)(R / (double)sx + K / (double)sz);
            g_ticket = 0;               // self-reset for next graph replay
        }
    }
}

// ---------------- launch ----------------
extern "C" void kernel_launch(void* const* d_in, const int* in_sizes, int n_in,
                              void* d_out, int out_size)
{
    const float* x      = (const float*)d_in[0];
    const int*   x_sl   = (const int*)  d_in[1];
    const float* ngrams = (const float*)d_in[4];
    const float* gumbel = (const float*)d_in[5];
    const float* W1     = (const float*)d_in[6];
    const float* b1     = (const float*)d_in[7];
    const float* W2     = (const float*)d_in[8];
    const float* b2     = (const float*)d_in[9];
    const float* Wd1    = (const float*)d_in[10];
    const float* bd1    = (const float*)d_in[11];
    const float* Wd2    = (const float*)d_in[12];
    const float* bd2    = (const float*)d_in[13];
    float* out = (float*)d_out;

    cudaFuncSetAttribute(k_enc_table, cudaFuncAttributeMaxDynamicSharedMemorySize,
                         ENC_SMEM_BYTES);

    k_enc_table<<<ENC_BLOCKS + TBL_BLOCKS, 512, ENC_SMEM_BYTES>>>(
        x, gumbel, W1, b1, W2, b2, Wd1, bd1, Wd2, bd2);
    k_loss<<<LOSS_BLOCKS, 256>>>(x, x_sl, ngrams, out);
}

// round 15
// speedup vs baseline: 1.5526x; 1.5526x over previous
#include <cuda_runtime.h>
#include <math.h>

#define BB 8
#define LL 48000
#define VV 28
#define QQ 256
#define CC 256
#define TT 960          // L / 50
#define NGD 29          // V + 1

#define ENC_BLOCKS 120          // 8 b * 15 chunks of 64 t
#define TR_BLOCKS  256
#define TBL_BLOCKS 150          // 15 i-groups (2 i each) x 10 j
#define LOSS_BLOCKS 1500        // 384000 / 256, 1 sample per thread

// ---------------- scratch ----------------
__device__ int    g_preds[BB * TT];
__device__ float  g_Wd2T[10 * 256 * 256];     // [j][c][q]
__device__ float  g_M[NGD * 5 * 10 * 256];    // logprob table: acc + bd2 - LSE
__device__ double g_prec[LOSS_BLOCKS];
__device__ double g_pkl[LOSS_BLOCKS];
__device__ int    g_ticket;                   // zero-init; self-resets each pass

// ---------------- f32x2 helpers ----------------
__device__ __forceinline__ void fma2(unsigned long long& d, unsigned long long a,
                                     unsigned long long b, unsigned long long c) {
    asm("fma.rn.f32x2 %0, %1, %2, %3;" : "=l"(d) : "l"(a), "l"(b), "l"(c));
}
__device__ __forceinline__ void add2(unsigned long long& d, unsigned long long a,
                                     unsigned long long b) {
    asm("add.rn.f32x2 %0, %1, %2;" : "=l"(d) : "l"(a), "l"(b));
}
__device__ __forceinline__ unsigned long long bcast2(float v) {
    unsigned long long r;
    asm("mov.b64 %0, {%1, %1};" : "=l"(r) : "f"(v));
    return r;
}
__device__ __forceinline__ void unpack2(unsigned long long v, float& lo, float& hi) {
    asm("mov.b64 {%0, %1}, %2;" : "=f"(lo), "=f"(hi) : "l"(v));
}

// ---------------- fused encoder + Wd2 transpose (identical to round 13) ----------------
#define W2STRIDE 164
#define W1STRIDE 14
#define ENC_T    64
#define LSTRIDE  33
#define W2S_OFF 0
#define W1S_OFF (256 * W2STRIDE)
#define XS_OFF  (W1S_OFF + 256 * W1STRIDE)
#define B1S_OFF (XS_OFF + ENC_T * 50)
#define B2S_OFF (B1S_OFF + 256)
#define LS_OFF  (B2S_OFF + 32)
#define ENC_SMEM_FLOATS (LS_OFF + ENC_T * LSTRIDE)
#define ENC_SMEM_BYTES  (ENC_SMEM_FLOATS * 4)       // ~204.7 KB

__global__ __launch_bounds__(512, 1)
void k_enc_tr(const float* __restrict__ x, const float* __restrict__ gumbel,
              const float* __restrict__ W1, const float* __restrict__ b1,
              const float* __restrict__ W2, const float* __restrict__ b2,
              const float* __restrict__ Wd2)
{
    extern __shared__ float sm[];
    const int tid = threadIdx.x;

    if (blockIdx.x >= ENC_BLOCKS) {
        // ----- transpose branch -----
        const int c = blockIdx.x - ENC_BLOCKS;
        float* tile = sm;
        for (int lin = tid; lin < 2560; lin += 512)
            tile[lin] = Wd2[c * 2560 + lin];        // coalesced read
        __syncthreads();
        if (tid < 256) {
            const int q = tid;
#pragma unroll
            for (int j = 0; j < 10; j++)
                g_Wd2T[j * 65536 + c * 256 + q] = tile[q * 10 + j];
        }
        return;
    }

    // ----- encoder branch (quarter-split) -----
    float* W2s = sm + W2S_OFF;
    float* W1s = sm + W1S_OFF;
    float* xs  = sm + XS_OFF;
    float* b1s = sm + B1S_OFF;
    float* b2s = sm + B2S_OFF;
    float* ls  = sm + LS_OFF;

    const int b   = blockIdx.x / 15;
    const int t0  = (blockIdx.x % 15) * ENC_T;

    for (int lin = tid; lin < 28 * 256 * 5; lin += 512) {
        int o = lin / 1280, rem = lin % 1280;
        int c = rem / 5,    kk  = rem % 5;
        int qd = o >> 3, oo = o & 7;
        W2s[c * W2STRIDE + qd * 40 + kk * 8 + oo] = W2[lin];
    }
    for (int lin = tid; lin < 256 * 5 * 4; lin += 512) {
        int c = lin / 20, kk = (lin % 20) / 4, oo = (lin % 4) + 4;
        W2s[c * W2STRIDE + 120 + kk * 8 + oo] = 0.f;
    }
    for (int lin = tid; lin < 2560; lin += 512)
        W1s[(lin / 10) * W1STRIDE + (lin % 10)] = W1[lin];
    for (int lin = tid; lin < ENC_T * 50; lin += 512)
        xs[lin] = x[b * LL + t0 * 50 + lin];
    if (tid < 256) b1s[tid] = b1[tid];
    if (tid < 28)  b2s[tid] = b2[tid];
    __syncthreads();

    const int s   = tid >> 3;     // slot 0..63, one t each
    const int cg  = tid & 7;      // channel group
    const int oq  = s & 3;        // o-quarter this lane accumulates

    const unsigned long long* xsp = (const unsigned long long*)(xs + 50 * s);
    unsigned long long xr2[25];
#pragma unroll
    for (int j = 0; j < 25; j++) xr2[j] = xsp[j];

    unsigned long long acc[4][4];
#pragma unroll
    for (int r = 0; r < 4; r++)
#pragma unroll
        for (int u = 0; u < 4; u++) acc[r][u] = 0ULL;

    for (int ci = 0; ci < 32; ci++) {
        const int c = cg + 8 * ci;
        const unsigned long long* w1p = (const unsigned long long*)(W1s + c * W1STRIDE);
        const float b1c = b1s[c];
        const float* wq = W2s + c * W2STRIDE + oq * 40;

#pragma unroll
        for (int kk = 0; kk < 5; kk++) {
            unsigned long long s2 = 0ULL;
#pragma unroll
            for (int k2 = 0; k2 < 5; k2++)
                fma2(s2, xr2[kk * 5 + k2], w1p[k2], s2);
            float lo, hi; unpack2(s2, lo, hi);
            const float h0 = fminf(fmaxf(lo + hi + b1c, 0.f), 6.f);
            const float h1 = __shfl_xor_sync(0xffffffffu, h0, 8);
            const float h2 = __shfl_xor_sync(0xffffffffu, h0, 16);
            const float h3 = __shfl_xor_sync(0xffffffffu, h1, 16);

            const ulonglong2* wp = (const ulonglong2*)(wq + kk * 8);
            const ulonglong2 w01 = wp[0];
            const ulonglong2 w23 = wp[1];

            const unsigned long long hp0 = bcast2(h0);
            const unsigned long long hp1 = bcast2(h1);
            const unsigned long long hp2 = bcast2(h2);
            const unsigned long long hp3 = bcast2(h3);

            fma2(acc[0][0], hp0, w01.x, acc[0][0]);
            fma2(acc[0][1], hp0, w01.y, acc[0][1]);
            fma2(acc[0][2], hp0, w23.x, acc[0][2]);
            fma2(acc[0][3], hp0, w23.y, acc[0][3]);
            fma2(acc[1][0], hp1, w01.x, acc[1][0]);
            fma2(acc[1][1], hp1, w01.y, acc[1][1]);
            fma2(acc[1][2], hp1, w23.x, acc[1][2]);
            fma2(acc[1][3], hp1, w23.y, acc[1][3]);
            fma2(acc[2][0], hp2, w01.x, acc[2][0]);
            fma2(acc[2][1], hp2, w01.y, acc[2][1]);
            fma2(acc[2][2], hp2, w23.x, acc[2][2]);
            fma2(acc[2][3], hp2, w23.y, acc[2][3]);
            fma2(acc[3][0], hp3, w01.x, acc[3][0]);
            fma2(acc[3][1], hp3, w01.y, acc[3][1]);
            fma2(acc[3][2], hp3, w23.x, acc[3][2]);
            fma2(acc[3][3], hp3, w23.y, acc[3][3]);
        }
    }

#pragma unroll
    for (int r = 0; r < 4; r++)
#pragma unroll
        for (int u = 0; u < 4; u++) {
            unsigned long long v = acc[r][u], o2;
            o2 = __shfl_xor_sync(0xffffffffu, v, 1); add2(v, v, o2);
            o2 = __shfl_xor_sync(0xffffffffu, v, 2); add2(v, v, o2);
            o2 = __shfl_xor_sync(0xffffffffu, v, 4); add2(v, v, o2);
            acc[r][u] = v;
        }

    if (cg == 0) {
        const int sbase = s & ~3;
#pragma unroll
        for (int r = 0; r < 4; r++) {
            const int tloc = sbase + ((s & 3) ^ r);
            float* lrow = ls + tloc * LSTRIDE + oq * 8;
#pragma unroll
            for (int u = 0; u < 4; u++) {
                float lo, hi; unpack2(acc[r][u], lo, hi);
                lrow[2 * u]     = lo;
                lrow[2 * u + 1] = hi;
            }
        }
    }
    __syncthreads();

    if (tid < ENC_T) {
        const int tg = t0 + tid;
        const float* g = gumbel + (b * TT + tg) * VV;
        const float* lrow = ls + tid * LSTRIDE;
        float best = -1e30f; int bi = 0;
#pragma unroll
        for (int o = 0; o < 28; o++) {
            float v = lrow[o] + b2s[o] + g[o];
            if (v > best) { best = v; bi = o; }
        }
        g_preds[b * TT + tg] = bi;
    }
}

// ---------------- decoder table, i-paired: 15 i-groups x 10 j ----------------
// Each block computes 2 i-rows per Wd2T word loaded (halves L2 traffic).
// Per-(i,j2,j,q) FP sequence identical to the 290-block version -> g_M bit-identical.
__global__ __launch_bounds__(256)
void k_table(const float* __restrict__ Wd1, const float* __restrict__ bd1,
             const float* __restrict__ bd2)
{
    __shared__ float rv[2 * 5 * 256];
    __shared__ float red[8];
    const int g   = blockIdx.x / 10;      // i-group: i = 2g, 2g+1
    const int j   = blockIdx.x % 10;
    const int tid = threadIdx.x;
    const int ibase = 2 * g;

    // stage both i-rows; i >= 28 gets w=0 (i=28 masked row; i=29 dummy, never stored)
    for (int lin = tid; lin < 2 * 1280; lin += 256) {
        int ii = lin / 1280, rem = lin % 1280;
        int c = rem / 5, j2 = rem % 5;
        int i = ibase + ii;
        float w = (i < VV) ? Wd1[i * 1280 + rem] : 0.f;
        rv[ii * 1280 + j2 * 256 + c] = fminf(fmaxf(w + bd1[c], 0.f), 6.f);
    }
    __syncthreads();

    float acc[2][5] = {{0.f,0.f,0.f,0.f,0.f},{0.f,0.f,0.f,0.f,0.f}};
    const float* wt = g_Wd2T + j * 65536 + tid;
#pragma unroll 8
    for (int c = 0; c < 256; c++) {
        float w = wt[c * 256];
#pragma unroll
        for (int j2 = 0; j2 < 5; j2++) {
            acc[0][j2] += rv[j2 * 256 + c] * w;
            acc[1][j2] += rv[1280 + j2 * 256 + c] * w;
        }
    }

    const float bdq  = bd2[tid];
    const int   lane = tid & 31, wid = tid >> 5;
    for (int ii = 0; ii < 2; ii++) {
        const int i = ibase + ii;
        if (i > 28) break;
        for (int j2 = 0; j2 < 5; j2++) {
            float v = acc[ii][j2] + bdq;
            float m = v;
            for (int s = 16; s > 0; s >>= 1)
                m = fmaxf(m, __shfl_xor_sync(0xffffffffu, m, s));
            if (lane == 0) red[wid] = m;
            __syncthreads();
            float mAll = red[0];
#pragma unroll
            for (int w2 = 1; w2 < 8; w2++) mAll = fmaxf(mAll, red[w2]);
            __syncthreads();
            float e = expf(v - mAll);
            for (int s = 16; s > 0; s >>= 1)
                e += __shfl_xor_sync(0xffffffffu, e, s);
            if (lane == 0) red[wid] = e;
            __syncthreads();
            float ssum = 0.f;
#pragma unroll
            for (int w2 = 0; w2 < 8; w2++) ssum += red[w2];
            const float lse = mAll + logf(ssum);
            g_M[(((i * 5 + j2) * 10 + j) * 256) + tid] = v - lse;
            __syncthreads();
        }
    }
}

// ---------------- loss (1 sample/thread, 1500 blocks) + fused final ----------------
__global__ __launch_bounds__(256)
void k_loss(const float* __restrict__ x, const int* __restrict__ x_sl,
            const float* __restrict__ ngrams, float* __restrict__ out)
{
    __shared__ double sr[8], sk[8];
    __shared__ int    isLast;
    const int tid = threadIdx.x;
    const int gid = blockIdx.x * 256 + tid;         // < 384000 exactly
    const int b   = gid / LL, l = gid % LL;
    const int sl  = x_sl[b];
    const int zsl = sl / 50;
    const int t   = l / 50;

    float rec = 0.f, kl = 0.f;

    if (l < sl) {
        const float xv = x[gid];
        float y = log1pf(255.f * fabsf(xv)) / 5.5451774444795625f;
        y = copysignf(y, xv);
        int tq = (int)floorf((y + 1.0f) * 0.5f * 256.0f);
        tq = min(max(tq, 0), 255);
        const int j2 = (l / 10) % 5;
        const int j  = l % 10;
        const int i  = (t < zsl) ? g_preds[b * TT + t] : 28;
        rec = -g_M[(((i * 5 + j2) * 10 + j) * 256) + tq];
    }

    if ((l % 50) == 0 && t < zsl) {
        const int p  = g_preds[b * TT + t];
        const int a0 = (t >= 2) ? g_preds[b * TT + t - 2] : 28;
        const int a1 = (t >= 1) ? g_preds[b * TT + t - 1] : 28;
        const float pr = ngrams[(a0 * 29 + a1) * 28 + p];
        kl = logf(1.0f / (pr + 1e-10f) + 1e-10f);
    }

    const int lane = tid & 31, wid = tid >> 5;
    for (int s = 16; s > 0; s >>= 1) {
        rec += __shfl_down_sync(0xffffffffu, rec, s);
        kl  += __shfl_down_sync(0xffffffffu, kl,  s);
    }
    if (lane == 0) { sr[wid] = (double)rec; sk[wid] = (double)kl; }
    __syncthreads();
    if (tid == 0) {
        double r = 0.0, k = 0.0;
#pragma unroll
        for (int w2 = 0; w2 < 8; w2++) { r += sr[w2]; k += sk[w2]; }
        g_prec[blockIdx.x] = r;
        g_pkl[blockIdx.x]  = k;
        __threadfence();
        int tck = atomicAdd(&g_ticket, 1);
        isLast = (tck == LOSS_BLOCKS - 1);
    }
    __syncthreads();

    if (isLast) {
        double r = 0.0, k = 0.0;
        for (int i = tid; i < LOSS_BLOCKS; i += 256) {
            r += __ldcg(&g_prec[i]);
            k += __ldcg(&g_pkl[i]);
        }
        for (int s = 16; s > 0; s >>= 1) {
            r += __shfl_down_sync(0xffffffffu, r, s);
            k += __shfl_down_sync(0xffffffffu, k, s);
        }
        __syncthreads();
        if (lane == 0) { sr[wid] = r; sk[wid] = k; }
        __syncthreads();
        if (tid == 0) {
            double R = 0.0, K = 0.0;
#pragma unroll
            for (int w2 = 0; w2 < 8; w2++) { R += sr[w2]; K += sk[w2]; }
            long long sx = 0, sz = 0;
#pragma unroll
            for (int bb = 0; bb < BB; bb++) { sx += x_sl[bb]; sz += x_sl[bb] / 50; }
            out[0] = (float)(R / (double)sx + K / (double)sz);
            g_ticket = 0;               // self-reset for next graph replay
        }
    }
}

// ---------------- launch ----------------
extern "C" void kernel_launch(void* const* d_in, const int* in_sizes, int n_in,
                              void* d_out, int out_size)
{
    const float* x      = (const float*)d_in[0];
    const int*   x_sl   = (const int*)  d_in[1];
    const float* ngrams = (const float*)d_in[4];
    const float* gumbel = (const float*)d_in[5];
    const float* W1     = (const float*)d_in[6];
    const float* b1     = (const float*)d_in[7];
    const float* W2     = (const float*)d_in[8];
    const float* b2     = (const float*)d_in[9];
    const float* Wd1    = (const float*)d_in[10];
    const float* bd1    = (const float*)d_in[11];
    const float* Wd2    = (const float*)d_in[12];
    const float* bd2    = (const float*)d_in[13];
    float* out = (float*)d_out;

    cudaFuncSetAttribute(k_enc_tr, cudaFuncAttributeMaxDynamicSharedMemorySize,
                         ENC_SMEM_BYTES);

    k_enc_tr<<<ENC_BLOCKS + TR_BLOCKS, 512, ENC_SMEM_BYTES>>>(
        x, gumbel, W1, b1, W2, b2, Wd2);
    k_table<<<TBL_BLOCKS, 256>>>(Wd1, bd1, bd2);
    k_loss<<<LOSS_BLOCKS, 256>>>(x, x_sl, ngrams, out);
}

// round 16
// speedup vs baseline: 1.8956x; 1.2209x over previous
#include <cuda_runtime.h>
#include <math.h>

#define BB 8
#define LL 48000
#define VV 28
#define QQ 256
#define CC 256
#define TT 960          // L / 50
#define NGD 29          // V + 1

#define ENC_BLOCKS 120          // 8 b * 15 chunks of 64 t
#define TR_BLOCKS  256
#define TR_END     (ENC_BLOCKS + TR_BLOCKS)    // 376
#define TBL_BLOCKS 290          // 29 i x 10 j
#define GRID1      (TR_END + TBL_BLOCKS)       // 666
#define LOSS_BLOCKS 1500        // 384000 / 256, 1 sample per thread

// ---------------- scratch ----------------
__device__ int    g_preds[BB * TT];
__device__ float  g_Wd2T[10 * 256 * 256];     // [j][c][q]
__device__ float  g_M[NGD * 5 * 10 * 256];    // logprob table: acc + bd2 - LSE
__device__ double g_prec[LOSS_BLOCKS];
__device__ double g_pkl[LOSS_BLOCKS];
__device__ int    g_ticket;                   // zero-init; reset by loss last block
__device__ int    g_trdone;                   // transpose-done counter; reset by loss

// ---------------- f32x2 helpers ----------------
__device__ __forceinline__ void fma2(unsigned long long& d, unsigned long long a,
                                     unsigned long long b, unsigned long long c) {
    asm("fma.rn.f32x2 %0, %1, %2, %3;" : "=l"(d) : "l"(a), "l"(b), "l"(c));
}
__device__ __forceinline__ void add2(unsigned long long& d, unsigned long long a,
                                     unsigned long long b) {
    asm("add.rn.f32x2 %0, %1, %2;" : "=l"(d) : "l"(a), "l"(b));
}
__device__ __forceinline__ unsigned long long bcast2(float v) {
    unsigned long long r;
    asm("mov.b64 %0, {%1, %1};" : "=l"(r) : "f"(v));
    return r;
}
__device__ __forceinline__ void unpack2(unsigned long long v, float& lo, float& hi) {
    asm("mov.b64 {%0, %1}, %2;" : "=f"(lo), "=f"(hi) : "l"(v));
}

// ---------------- encoder smem layout (quarter-split, proven) ----------------
#define W2STRIDE 164
#define W1STRIDE 14
#define ENC_T    64
#define LSTRIDE  33
#define W2S_OFF 0
#define W1S_OFF (256 * W2STRIDE)
#define XS_OFF  (W1S_OFF + 256 * W1STRIDE)
#define B1S_OFF (XS_OFF + ENC_T * 50)
#define B2S_OFF (B1S_OFF + 256)
#define LS_OFF  (B2S_OFF + 32)
#define ENC_SMEM_FLOATS (LS_OFF + ENC_T * LSTRIDE)
#define ENC_SMEM_BYTES  (ENC_SMEM_FLOATS * 4)       // ~204.7 KB

// ---------------- fused encoder + transpose + decoder table ----------------
__global__ __launch_bounds__(512, 1)
void k_enc_all(const float* __restrict__ x, const float* __restrict__ gumbel,
               const float* __restrict__ W1, const float* __restrict__ b1,
               const float* __restrict__ W2, const float* __restrict__ b2,
               const float* __restrict__ Wd2, const float* __restrict__ Wd1,
               const float* __restrict__ bd1, const float* __restrict__ bd2)
{
    extern __shared__ float sm[];
    const int tid = threadIdx.x;

    if (blockIdx.x >= TR_END) {
        // ===== table branch: one (i,j); waits for transpose, c split over halves =====
        const int bi = blockIdx.x - TR_END;
        const int i = bi / 10, j = bi % 10;
        float* rv   = sm;            // 1280
        float* part = sm + 1280;     // 1280
        float* red  = sm + 2560;     // 8

        if (tid == 0)
            while (*(volatile int*)&g_trdone < TR_BLOCKS) __nanosleep(64);
        __syncthreads();

        for (int lin = tid; lin < 1280; lin += 512) {
            int c = lin / 5, j2 = lin % 5;
            float w = (i < VV) ? Wd1[i * 1280 + lin] : 0.f;
            rv[j2 * 256 + c] = fminf(fmaxf(w + bd1[c], 0.f), 6.f);
        }
        __syncthreads();

        const int half = tid >> 8;       // 0: c 0..127, 1: c 128..255
        const int q    = tid & 255;
        float acc[5] = {0.f, 0.f, 0.f, 0.f, 0.f};
        const float* wt = g_Wd2T + j * 65536 + half * (128 * 256) + q;
#pragma unroll 16
        for (int c = 0; c < 128; c++) {
            float w = __ldcg(wt + c * 256);
#pragma unroll
            for (int j2 = 0; j2 < 5; j2++)
                acc[j2] += rv[j2 * 256 + half * 128 + c] * w;
        }
        if (half) {
#pragma unroll
            for (int j2 = 0; j2 < 5; j2++) part[j2 * 256 + q] = acc[j2];
        }
        __syncthreads();
        if (!half) {
#pragma unroll
            for (int j2 = 0; j2 < 5; j2++) acc[j2] += part[j2 * 256 + q];
        }

        const float bdq  = bd2[q];
        const int   lane = tid & 31, wid = tid >> 5;
        for (int j2 = 0; j2 < 5; j2++) {
            float v = 0.f;
            if (!half) {
                v = acc[j2] + bdq;
                float m = v;
                for (int s = 16; s > 0; s >>= 1)
                    m = fmaxf(m, __shfl_xor_sync(0xffffffffu, m, s));
                if (lane == 0) red[wid] = m;
            }
            __syncthreads();
            float mAll = red[0];
#pragma unroll
            for (int w2 = 1; w2 < 8; w2++) mAll = fmaxf(mAll, red[w2]);
            __syncthreads();
            if (!half) {
                float e = expf(v - mAll);
                for (int s = 16; s > 0; s >>= 1)
                    e += __shfl_xor_sync(0xffffffffu, e, s);
                if (lane == 0) red[wid] = e;
            }
            __syncthreads();
            if (!half) {
                float ssum = 0.f;
#pragma unroll
                for (int w2 = 0; w2 < 8; w2++) ssum += red[w2];
                g_M[((i * 5 + j2) * 10 + j) * 256 + q] = v - (mAll + logf(ssum));
            }
            __syncthreads();
        }
        return;
    }

    if (blockIdx.x >= ENC_BLOCKS) {
        // ===== transpose branch =====
        const int c = blockIdx.x - ENC_BLOCKS;
        float* tile = sm;
        for (int lin = tid; lin < 2560; lin += 512)
            tile[lin] = Wd2[c * 2560 + lin];        // coalesced read
        __syncthreads();
        if (tid < 256) {
            const int q = tid;
#pragma unroll
            for (int j = 0; j < 10; j++)
                g_Wd2T[j * 65536 + c * 256 + q] = tile[q * 10 + j];
        }
        __threadfence();
        __syncthreads();
        if (tid == 0) atomicAdd(&g_trdone, 1);
        return;
    }

    // ===== encoder branch (quarter-split, byte-identical to round 13) =====
    float* W2s = sm + W2S_OFF;
    float* W1s = sm + W1S_OFF;
    float* xs  = sm + XS_OFF;
    float* b1s = sm + B1S_OFF;
    float* b2s = sm + B2S_OFF;
    float* ls  = sm + LS_OFF;

    const int b   = blockIdx.x / 15;
    const int t0  = (blockIdx.x % 15) * ENC_T;

    for (int lin = tid; lin < 28 * 256 * 5; lin += 512) {
        int o = lin / 1280, rem = lin % 1280;
        int c = rem / 5,    kk  = rem % 5;
        int qd = o >> 3, oo = o & 7;
        W2s[c * W2STRIDE + qd * 40 + kk * 8 + oo] = W2[lin];
    }
    for (int lin = tid; lin < 256 * 5 * 4; lin += 512) {
        int c = lin / 20, kk = (lin % 20) / 4, oo = (lin % 4) + 4;
        W2s[c * W2STRIDE + 120 + kk * 8 + oo] = 0.f;
    }
    for (int lin = tid; lin < 2560; lin += 512)
        W1s[(lin / 10) * W1STRIDE + (lin % 10)] = W1[lin];
    for (int lin = tid; lin < ENC_T * 50; lin += 512)
        xs[lin] = x[b * LL + t0 * 50 + lin];
    if (tid < 256) b1s[tid] = b1[tid];
    if (tid < 28)  b2s[tid] = b2[tid];
    __syncthreads();

    const int s   = tid >> 3;
    const int cg  = tid & 7;
    const int oq  = s & 3;

    const unsigned long long* xsp = (const unsigned long long*)(xs + 50 * s);
    unsigned long long xr2[25];
#pragma unroll
    for (int j = 0; j < 25; j++) xr2[j] = xsp[j];

    unsigned long long acc[4][4];
#pragma unroll
    for (int r = 0; r < 4; r++)
#pragma unroll
        for (int u = 0; u < 4; u++) acc[r][u] = 0ULL;

    for (int ci = 0; ci < 32; ci++) {
        const int c = cg + 8 * ci;
        const unsigned long long* w1p = (const unsigned long long*)(W1s + c * W1STRIDE);
        const float b1c = b1s[c];
        const float* wq = W2s + c * W2STRIDE + oq * 40;

#pragma unroll
        for (int kk = 0; kk < 5; kk++) {
            unsigned long long s2 = 0ULL;
#pragma unroll
            for (int k2 = 0; k2 < 5; k2++)
                fma2(s2, xr2[kk * 5 + k2], w1p[k2], s2);
            float lo, hi; unpack2(s2, lo, hi);
            const float h0 = fminf(fmaxf(lo + hi + b1c, 0.f), 6.f);
            const float h1 = __shfl_xor_sync(0xffffffffu, h0, 8);
            const float h2 = __shfl_xor_sync(0xffffffffu, h0, 16);
            const float h3 = __shfl_xor_sync(0xffffffffu, h1, 16);

            const ulonglong2* wp = (const ulonglong2*)(wq + kk * 8);
            const ulonglong2 w01 = wp[0];
            const ulonglong2 w23 = wp[1];

            const unsigned long long hp0 = bcast2(h0);
            const unsigned long long hp1 = bcast2(h1);
            const unsigned long long hp2 = bcast2(h2);
            const unsigned long long hp3 = bcast2(h3);

            fma2(acc[0][0], hp0, w01.x, acc[0][0]);
            fma2(acc[0][1], hp0, w01.y, acc[0][1]);
            fma2(acc[0][2], hp0, w23.x, acc[0][2]);
            fma2(acc[0][3], hp0, w23.y, acc[0][3]);
            fma2(acc[1][0], hp1, w01.x, acc[1][0]);
            fma2(acc[1][1], hp1, w01.y, acc[1][1]);
            fma2(acc[1][2], hp1, w23.x, acc[1][2]);
            fma2(acc[1][3], hp1, w23.y, acc[1][3]);
            fma2(acc[2][0], hp2, w01.x, acc[2][0]);
            fma2(acc[2][1], hp2, w01.y, acc[2][1]);
            fma2(acc[2][2], hp2, w23.x, acc[2][2]);
            fma2(acc[2][3], hp2, w23.y, acc[2][3]);
            fma2(acc[3][0], hp3, w01.x, acc[3][0]);
            fma2(acc[3][1], hp3, w01.y, acc[3][1]);
            fma2(acc[3][2], hp3, w23.x, acc[3][2]);
            fma2(acc[3][3], hp3, w23.y, acc[3][3]);
        }
    }

#pragma unroll
    for (int r = 0; r < 4; r++)
#pragma unroll
        for (int u = 0; u < 4; u++) {
            unsigned long long v = acc[r][u], o2;
            o2 = __shfl_xor_sync(0xffffffffu, v, 1); add2(v, v, o2);
            o2 = __shfl_xor_sync(0xffffffffu, v, 2); add2(v, v, o2);
            o2 = __shfl_xor_sync(0xffffffffu, v, 4); add2(v, v, o2);
            acc[r][u] = v;
        }

    if (cg == 0) {
        const int sbase = s & ~3;
#pragma unroll
        for (int r = 0; r < 4; r++) {
            const int tloc = sbase + ((s & 3) ^ r);
            float* lrow = ls + tloc * LSTRIDE + oq * 8;
#pragma unroll
            for (int u = 0; u < 4; u++) {
                float lo, hi; unpack2(acc[r][u], lo, hi);
                lrow[2 * u]     = lo;
                lrow[2 * u + 1] = hi;
            }
        }
    }
    __syncthreads();

    if (tid < ENC_T) {
        const int tg = t0 + tid;
        const float* g = gumbel + (b * TT + tg) * VV;
        const float* lrow = ls + tid * LSTRIDE;
        float best = -1e30f; int bi2 = 0;
#pragma unroll
        for (int o = 0; o < 28; o++) {
            float v = lrow[o] + b2s[o] + g[o];
            if (v > best) { best = v; bi2 = o; }
        }
        g_preds[b * TT + tg] = bi2;
    }
}

// ---------------- loss (1 sample/thread, 1500 blocks) + fused final ----------------
__global__ __launch_bounds__(256)
void k_loss(const float* __restrict__ x, const int* __restrict__ x_sl,
            const float* __restrict__ ngrams, float* __restrict__ out)
{
    __shared__ double sr[8], sk[8];
    __shared__ int    isLast;
    const int tid = threadIdx.x;
    const int gid = blockIdx.x * 256 + tid;         // < 384000 exactly
    const int b   = gid / LL, l = gid % LL;
    const int sl  = x_sl[b];
    const int zsl = sl / 50;
    const int t   = l / 50;

    float rec = 0.f, kl = 0.f;

    if (l < sl) {
        const float xv = x[gid];
        float y = log1pf(255.f * fabsf(xv)) / 5.5451774444795625f;
        y = copysignf(y, xv);
        int tq = (int)floorf((y + 1.0f) * 0.5f * 256.0f);
        tq = min(max(tq, 0), 255);
        const int j2 = (l / 10) % 5;
        const int j  = l % 10;
        const int i  = (t < zsl) ? g_preds[b * TT + t] : 28;
        rec = -g_M[(((i * 5 + j2) * 10 + j) * 256) + tq];
    }

    if ((l % 50) == 0 && t < zsl) {
        const int p  = g_preds[b * TT + t];
        const int a0 = (t >= 2) ? g_preds[b * TT + t - 2] : 28;
        const int a1 = (t >= 1) ? g_preds[b * TT + t - 1] : 28;
        const float pr = ngrams[(a0 * 29 + a1) * 28 + p];
        kl = logf(1.0f / (pr + 1e-10f) + 1e-10f);
    }

    const int lane = tid & 31, wid = tid >> 5;
    for (int s = 16; s > 0; s >>= 1) {
        rec += __shfl_down_sync(0xffffffffu, rec, s);
        kl  += __shfl_down_sync(0xffffffffu, kl,  s);
    }
    if (lane == 0) { sr[wid] = (double)rec; sk[wid] = (double)kl; }
    __syncthreads();
    if (tid == 0) {
        double r = 0.0, k = 0.0;
#pragma unroll
        for (int w2 = 0; w2 < 8; w2++) { r += sr[w2]; k += sk[w2]; }
        g_prec[blockIdx.x] = r;
        g_pkl[blockIdx.x]  = k;
        __threadfence();
        int tck = atomicAdd(&g_ticket, 1);
        isLast = (tck == LOSS_BLOCKS - 1);
    }
    __syncthreads();

    if (isLast) {
        double r = 0.0, k = 0.0;
        for (int i = tid; i < LOSS_BLOCKS; i += 256) {
            r += __ldcg(&g_prec[i]);
            k += __ldcg(&g_pkl[i]);
        }
        for (int s = 16; s > 0; s >>= 1) {
            r += __shfl_down_sync(0xffffffffu, r, s);
            k += __shfl_down_sync(0xffffffffu, k, s);
        }
        __syncthreads();
        if (lane == 0) { sr[wid] = r; sk[wid] = k; }
        __syncthreads();
        if (tid == 0) {
            double R = 0.0, K = 0.0;
#pragma unroll
            for (int w2 = 0; w2 < 8; w2++) { R += sr[w2]; K += sk[w2]; }
            long long sx = 0, sz = 0;
#pragma unroll
            for (int bb = 0; bb < BB; bb++) { sx += x_sl[bb]; sz += x_sl[bb] / 50; }
            out[0] = (float)(R / (double)sx + K / (double)sz);
            g_ticket = 0;               // self-reset for next graph replay
            g_trdone = 0;
        }
    }
}

// ---------------- launch ----------------
extern "C" void kernel_launch(void* const* d_in, const int* in_sizes, int n_in,
                              void* d_out, int out_size)
{
    const float* x      = (const float*)d_in[0];
    const int*   x_sl   = (const int*)  d_in[1];
    const float* ngrams = (const float*)d_in[4];
    const float* gumbel = (const float*)d_in[5];
    const float* W1     = (const float*)d_in[6];
    const float* b1     = (const float*)d_in[7];
    const float* W2     = (const float*)d_in[8];
    const float* b2     = (const float*)d_in[9];
    const float* Wd1    = (const float*)d_in[10];
    const float* bd1    = (const float*)d_in[11];
    const float* Wd2    = (const float*)d_in[12];
    const float* bd2    = (const float*)d_in[13];
    float* out = (float*)d_out;

    cudaFuncSetAttribute(k_enc_all, cudaFuncAttributeMaxDynamicSharedMemorySize,
                         ENC_SMEM_BYTES);

    k_enc_all<<<GRID1, 512, ENC_SMEM_BYTES>>>(
        x, gumbel, W1, b1, W2, b2, Wd2, Wd1, bd1, bd2);
    k_loss<<<LOSS_BLOCKS, 256>>>(x, x_sl, ngrams, out);
}